// round 3
// baseline (speedup 1.0000x reference)
#include <cuda_runtime.h>

#define NL 51
#define LS 53
#define STARTI 51
#define ENDI 52
#define LOG2E 1.4426950408889634f
#define LN2   0.6931471805599453f

typedef unsigned long long ull;

__device__ __forceinline__ ull f2pack(float lo, float hi) {
    ull u;
    asm("mov.b64 %0, {%1, %2};" : "=l"(u) : "f"(lo), "f"(hi));
    return u;
}
__device__ __forceinline__ void f2fma(ull& d, ull a, ull b) {
    asm("fma.rn.f32x2 %0, %1, %2, %0;" : "+l"(d) : "l"(a), "l"(b));
}
__device__ __forceinline__ ull f2add(ull a, ull b) {
    ull d;
    asm("add.rn.f32x2 %0, %1, %2;" : "=l"(d) : "l"(a), "l"(b));
    return d;
}
__device__ __forceinline__ float2 f2unpack(ull u) {
    float lo, hi;
    asm("mov.b64 {%0, %1}, %2;" : "=f"(lo), "=f"(hi) : "l"(u));
    return make_float2(lo, hi);
}
__device__ __forceinline__ float ex2_approx(float x) {
    float r;
    asm("ex2.approx.f32 %0, %1;" : "=f"(r) : "f"(x));
    return r;
}

// ---------------------------------------------------------------------------
// Gold score: out[b] = sum_unary + sum_binary  (fully parallel gather+reduce)
// ---------------------------------------------------------------------------
__global__ void crf_gold(const float* __restrict__ logits,
                         const int* __restrict__ labels,
                         const int* __restrict__ lens,
                         const float* __restrict__ T,
                         float* __restrict__ out, int S)
{
    __shared__ float sT[LS * LS];
    __shared__ float red[8];
    int b = blockIdx.x, tid = threadIdx.x;
    for (int i = tid; i < LS * LS; i += blockDim.x) sT[i] = T[i];
    __syncthreads();

    int len = lens[b];
    if (len < 1) len = 1;
    if (len > S) len = S;

    const int*   lab = labels + (size_t)b * S;
    const float* lg  = logits + (size_t)b * S * NL;

    float s = 0.f;
    for (int j = tid; j <= len; j += 256) {
        int from = (j == 0)   ? STARTI : lab[j - 1];
        int to   = (j == len) ? ENDI   : lab[j];
        s += sT[to * LS + from];
        if (j < len) s += lg[(size_t)j * NL + to];
    }
    #pragma unroll
    for (int o = 16; o; o >>= 1) s += __shfl_xor_sync(0xffffffffu, s, o);
    if ((tid & 31) == 0) red[tid >> 5] = s;
    __syncthreads();
    if (tid == 0) {
        float v = 0.f;
        #pragma unroll
        for (int i = 0; i < 8; i++) v += red[i];
        out[b] = v;
    }
}

// ---------------------------------------------------------------------------
// Forward recursion, exp domain, power-of-2 renormalization.
// One WARP per batch element (2 warps / CTA on separate SMSPs, no bar.sync).
// Dense rows (O, 25xB, START) -> lanes 0..26, one 54-wide packed dot each.
// Sparse rows (I-Tk: single predecessor B-Tk) -> one multiply on lanes 0..24.
// END row never feeds the recursion (w[END] == 0 throughout).
// ---------------------------------------------------------------------------
__global__ void __launch_bounds__(64) crf_fwd(const float* __restrict__ logits,
                                              const int* __restrict__ lens,
                                              const float* __restrict__ T,
                                              float* __restrict__ out, int S)
{
    __shared__ __align__(16) float shw[2][2][56];   // [warp][buf][56]

    const int warp = threadIdx.x >> 5;
    const int lane = threadIdx.x & 31;
    const int b    = blockIdx.x * 2 + warp;

    int len = lens[b];
    if (len < 1) len = 1;
    if (len > S) len = S;

    const float* lg = logits + (size_t)b * S * NL;

    const bool isDense  = (lane < 27);
    const bool isStart  = (lane == 26);
    const bool isSparse = (lane < 25);
    const bool loadD    = isDense && !isStart;

    const int dstate = (lane == 0) ? 0 : (lane < 26 ? 2 * lane - 1 : STARTI);
    const int sstate = 2 * lane + 2;                 // I-T<lane>
    const int ssrc   = isSparse ? (sstate - 1) : 0;  // B-T<lane>

    // ---- precompute E row (dense lanes) + per-row constants ----
    ull   E[28];
    float TmaxL2d = 0.f, TmaxL2s = 0.f;
    if (isDense) {
        const float* row = T + dstate * LS;
        float m = row[0];
        #pragma unroll
        for (int f = 1; f < LS; f++) m = fmaxf(m, row[f]);
        #pragma unroll
        for (int p = 0; p < 28; p++) {
            int f0 = 2 * p, f1 = f0 + 1;
            float a = (f0 < LS) ? __expf(row[f0] - m) : 0.f;
            float c = (f1 < LS) ? __expf(row[f1] - m) : 0.f;
            E[p] = f2pack(a, c);
        }
        TmaxL2d = isStart ? 0.f : m * LOG2E;   // START: G == 1 (pad logit -100 + Tmax 100)
    } else {
        #pragma unroll
        for (int p = 0; p < 28; p++) E[p] = 0ull;
    }
    if (isSparse) TmaxL2s = T[sstate * LS + ssrc] * LOG2E;

    // ---- init state: w = e_START ----
    #pragma unroll
    for (int i = lane; i < 112; i += 32) (&shw[warp][0][0])[i] = 0.f;
    if (lane == 0) shw[warp][0][STARTI] = 1.f;

    // ---- 3-deep logit prefetch ----
    float gd0 = 0.f, gd1 = 0.f, gd2 = 0.f;
    float gs0 = 0.f, gs1 = 0.f, gs2 = 0.f;
    if (loadD) {
        gd0 = lg[dstate];
        if (1 < len) gd1 = lg[NL + dstate];
        if (2 < len) gd2 = lg[2 * NL + dstate];
    }
    if (isSparse) {
        gs0 = lg[sstate];
        if (1 < len) gs1 = lg[NL + sstate];
        if (2 < len) gs2 = lg[2 * NL + sstate];
    }

    int A = 0;   // exact sum of power-of-2 renormalization exponents
    __syncwarp();

    for (int t = 0; t < len; t++) {
        const float* win  = shw[warp][t & 1];
        float*       wout = shw[warp][(t & 1) ^ 1];

        // load full state vector (broadcast LDS.128 x14)
        const ulonglong2* wv = reinterpret_cast<const ulonglong2*>(win);
        ulonglong2 v[14];
        #pragma unroll
        for (int j = 0; j < 14; j++) v[j] = wv[j];

        // renorm scale from w[START] exponent (exact, ALU-only)
        float w51 = f2unpack(v[12].y).y;
        int   k   = (int)((__float_as_uint(w51) >> 23) & 255u) - 127;
        float scale = __int_as_float((unsigned)(127 - k) << 23);
        A += k;

        // G factors (off critical path: inputs prefetched)
        float GDs = ex2_approx(__fmaf_rn(gd0, LOG2E, TmaxL2d)) * scale;
        float GSs = ex2_approx(__fmaf_rn(gs0, LOG2E, TmaxL2s)) * scale;

        // dense 56-wide packed dot
        ull a0 = 0, a1 = 0, a2 = 0, a3 = 0;
        #pragma unroll
        for (int j = 0; j < 14; j += 2) {
            f2fma(a0, E[2 * j],     v[j].x);
            f2fma(a1, E[2 * j + 1], v[j].y);
            f2fma(a2, E[2 * j + 2], v[j + 1].x);
            f2fma(a3, E[2 * j + 3], v[j + 1].y);
        }
        float2 p = f2unpack(f2add(f2add(a0, a1), f2add(a2, a3)));
        float  s = p.x + p.y;

        float wn  = GDs * s;
        float wns = GSs * win[ssrc];

        if (isDense)  wout[dstate] = wn;
        if (isSparse) wout[sstate] = wns;

        // shift prefetch pipeline
        gd0 = gd1; gd1 = gd2;
        gs0 = gs1; gs1 = gs2;
        int tn = t + 3;
        gd2 = (loadD    && tn < len) ? lg[(size_t)tn * NL + dstate] : 0.f;
        gs2 = (isSparse && tn < len) ? lg[(size_t)tn * NL + sstate] : 0.f;

        __syncwarp();
    }

    // ---- END contraction + output ----
    if (lane == 0) {
        const float* wfin = shw[warp][len & 1];
        const float* rowE = T + ENDI * LS;
        float dot = 0.f;
        #pragma unroll 4
        for (int f = 0; f < LS; f++)
            dot += __expf(rowE[f] - 100.f) * wfin[f];
        float norm = (float)A * LN2 + 100.f + __logf(dot);
        out[b] = out[b] - norm;
    }
}

extern "C" void kernel_launch(void* const* d_in, const int* in_sizes, int n_in,
                              void* d_out, int out_size)
{
    const float* logits = (const float*)d_in[0];
    const int*   labels = (const int*)d_in[1];
    const int*   lens   = (const int*)d_in[2];
    const float* T      = (const float*)d_in[3];
    float*       out    = (float*)d_out;

    int B = out_size;                       // 256
    int S = in_sizes[1] / B;                // 2048

    crf_gold<<<B, 256>>>(logits, labels, lens, T, out, S);
    crf_fwd <<<B / 2, 64>>>(logits, lens, T, out, S);
}

// round 4
// speedup vs baseline: 1.5869x; 1.5869x over previous
#include <cuda_runtime.h>

#define NL 51
#define LS 53
#define STARTI 51
#define ENDI 52
#define LOG2E 1.4426950408889634f
#define LN2   0.6931471805599453f

typedef unsigned long long ull;

__device__ __forceinline__ ull f2pack(float lo, float hi) {
    ull u;
    asm("mov.b64 %0, {%1, %2};" : "=l"(u) : "f"(lo), "f"(hi));
    return u;
}
__device__ __forceinline__ void f2fma(ull& d, ull a, ull b) {
    asm("fma.rn.f32x2 %0, %1, %2, %0;" : "+l"(d) : "l"(a), "l"(b));
}
__device__ __forceinline__ ull f2add(ull a, ull b) {
    ull d;
    asm("add.rn.f32x2 %0, %1, %2;" : "=l"(d) : "l"(a), "l"(b));
    return d;
}
__device__ __forceinline__ float2 f2unpack(ull u) {
    float lo, hi;
    asm("mov.b64 {%0, %1}, %2;" : "=f"(lo), "=f"(hi) : "l"(u));
    return make_float2(lo, hi);
}
__device__ __forceinline__ float ex2_approx(float x) {
    float r;
    asm("ex2.approx.f32 %0, %1;" : "=f"(r) : "f"(x));
    return r;
}

// ---------------------------------------------------------------------------
// Gold score (parallel gather+reduce) — cheap, unchanged.
// ---------------------------------------------------------------------------
__global__ void crf_gold(const float* __restrict__ logits,
                         const int* __restrict__ labels,
                         const int* __restrict__ lens,
                         const float* __restrict__ T,
                         float* __restrict__ out, int S)
{
    __shared__ float sT[LS * LS];
    __shared__ float red[8];
    int b = blockIdx.x, tid = threadIdx.x;
    for (int i = tid; i < LS * LS; i += blockDim.x) sT[i] = T[i];
    __syncthreads();

    int len = lens[b];
    if (len < 1) len = 1;
    if (len > S) len = S;

    const int*   lab = labels + (size_t)b * S;
    const float* lg  = logits + (size_t)b * S * NL;

    float s = 0.f;
    for (int j = tid; j <= len; j += 256) {
        int from = (j == 0)   ? STARTI : lab[j - 1];
        int to   = (j == len) ? ENDI   : lab[j];
        s += sT[to * LS + from];
        if (j < len) s += lg[(size_t)j * NL + to];
    }
    #pragma unroll
    for (int o = 16; o; o >>= 1) s += __shfl_xor_sync(0xffffffffu, s, o);
    if ((tid & 31) == 0) red[tid >> 5] = s;
    __syncthreads();
    if (tid == 0) {
        float v = 0.f;
        #pragma unroll
        for (int i = 0; i < 8; i++) v += red[i];
        out[b] = v;
    }
}

// ---------------------------------------------------------------------------
// Forward recursion: one warp per chain, FULLY BRANCHLESS inner loop.
// Dense rows (O, 25xB, START) on lanes 0..26 (full 56-wide packed dot);
// sparse rows (I-Tk, single predecessor B-Tk) piggybacked on lanes 0..24.
// Lanes without a real row write to dummy slots [56..79]; loads read [0..55].
// Power-of-2 renorm via ALU exponent extraction (no MUFU on critical path).
// ---------------------------------------------------------------------------
__global__ void __launch_bounds__(64) crf_fwd(const float* __restrict__ logits,
                                              const int* __restrict__ lens,
                                              const float* __restrict__ T,
                                              float* __restrict__ out, int S)
{
    __shared__ __align__(16) float shw[2][2][80];   // [warp][buf][80]

    const int warp = threadIdx.x >> 5;
    const int lane = threadIdx.x & 31;
    const int b    = blockIdx.x * 2 + warp;

    int len = lens[b];
    if (len < 1) len = 1;
    if (len > S) len = S;
    const int lenm1 = len - 1;

    const float* lg = logits + (size_t)b * S * NL;

    // ---- lane role tables (computed once, all loads/stores in-bounds) ----
    const int  dstate = (lane == 0) ? 0 : (lane < 26 ? 2 * lane - 1 : STARTI);
    const int  sstate = (lane < 25) ? (2 * lane + 2) : 52;   // clamped
    const int  ssrc   = (lane < 25) ? (sstate - 1) : 0;
    const int  dslot  = (lane < 27) ? dstate : (48 + lane);  // dummies 75..79
    const int  sslot  = (lane < 25) ? sstate : (31 + lane);  // dummies 56..62
    const int  dld    = (dstate < NL) ? dstate : 0;          // logit-load state
    const int  sld    = (sstate < NL) ? sstate : 0;
    const float maskD = (lane < 26) ? 1.f : 0.f;             // START & pad: G=1
    const float maskS = (lane < 25) ? 1.f : 0.f;

    // ---- precompute E row + constants ----
    ull   E[28];
    float TmaxL2d, TmaxL2s;
    {
        const float* row = T + dstate * LS;
        float m = row[0];
        #pragma unroll
        for (int f = 1; f < LS; f++) m = fmaxf(m, row[f]);
        #pragma unroll
        for (int p = 0; p < 28; p++) {
            int f0 = 2 * p, f1 = f0 + 1;
            float a = (f0 < LS) ? __expf(row[f0] - m) : 0.f;
            float c = (f1 < LS) ? __expf(row[f1] - m) : 0.f;
            E[p] = f2pack(a, c);
        }
        TmaxL2d = (lane < 26) ? m * LOG2E : 0.f;   // START/pad: G = 2^0 = 1
        TmaxL2s = T[sstate * LS + ssrc] * LOG2E * maskS;
    }

    // ---- init state ----
    float* buf0 = &shw[warp][0][0];
    float* buf1 = &shw[warp][1][0];
    #pragma unroll
    for (int i = lane; i < 160; i += 32) buf0[i] = 0.f;   // zero both buffers
    if (lane == 0) buf0[STARTI] = 1.f;

    // ---- 3-deep clamped prefetch ----
    float gd0, gd1, gd2, gs0, gs1, gs2;
    {
        int i1 = min(1, lenm1), i2 = min(2, lenm1);
        gd0 = lg[dld] * maskD;
        gs0 = lg[sld] * maskS;
        gd1 = lg[(size_t)i1 * NL + dld] * maskD;
        gs1 = lg[(size_t)i1 * NL + sld] * maskS;
        gd2 = lg[(size_t)i2 * NL + dld] * maskD;
        gs2 = lg[(size_t)i2 * NL + sld] * maskS;
    }

    int A = 0;   // raw exponent-bit accumulator
    __syncwarp();

#define CRF_STEP(WIN, WOUT, T_CUR)                                            \
    {                                                                         \
        const ulonglong2* wv = reinterpret_cast<const ulonglong2*>(WIN);      \
        ulonglong2 v[14];                                                     \
        _Pragma("unroll")                                                     \
        for (int j = 0; j < 14; j++) v[j] = wv[j];                            \
        unsigned bits = __float_as_uint(f2unpack(v[12].y).y);                 \
        float scale = __int_as_float(0x7F000000u - (bits & 0x7F800000u));     \
        A += (int)(bits >> 23);                                               \
        float GD = ex2_approx(__fmaf_rn(gd0, LOG2E, TmaxL2d)) * scale;        \
        float GS = ex2_approx(__fmaf_rn(gs0, LOG2E, TmaxL2s)) * scale;        \
        ull a0 = 0, a1 = 0, a2 = 0, a3 = 0;                                   \
        _Pragma("unroll")                                                     \
        for (int j = 0; j < 14; j += 2) {                                     \
            f2fma(a0, E[2 * j],     v[j].x);                                  \
            f2fma(a1, E[2 * j + 1], v[j].y);                                  \
            f2fma(a2, E[2 * j + 2], v[j + 1].x);                              \
            f2fma(a3, E[2 * j + 3], v[j + 1].y);                              \
        }                                                                     \
        float2 pp = f2unpack(f2add(f2add(a0, a1), f2add(a2, a3)));            \
        (WOUT)[dslot] = GD * (pp.x + pp.y);                                   \
        (WOUT)[sslot] = GS * (WIN)[ssrc];                                     \
        gd0 = gd1; gd1 = gd2; gs0 = gs1; gs1 = gs2;                           \
        int tn = min((T_CUR) + 3, lenm1);                                     \
        const float* lgn = lg + (size_t)tn * NL;                              \
        gd2 = lgn[dld] * maskD;                                               \
        gs2 = lgn[sld] * maskS;                                               \
        __syncwarp();                                                         \
    }

    int t = 0;
    while (t + 2 <= len) {
        CRF_STEP(buf0, buf1, t);
        CRF_STEP(buf1, buf0, t + 1);
        t += 2;
    }
    if (t < len) {
        CRF_STEP(buf0, buf1, t);
    }
#undef CRF_STEP

    // ---- END contraction + output ----
    if (lane == 0) {
        const float* wfin = (len & 1) ? buf1 : buf0;
        const float* rowE = T + ENDI * LS;
        float dot = 0.f;
        #pragma unroll 4
        for (int f = 0; f < LS; f++)
            dot += __expf(rowE[f] - 100.f) * wfin[f];
        float norm = (float)(A - 127 * len) * LN2 + 100.f + __logf(dot);
        out[b] = out[b] - norm;
    }
}

extern "C" void kernel_launch(void* const* d_in, const int* in_sizes, int n_in,
                              void* d_out, int out_size)
{
    const float* logits = (const float*)d_in[0];
    const int*   labels = (const int*)d_in[1];
    const int*   lens   = (const int*)d_in[2];
    const float* T      = (const float*)d_in[3];
    float*       out    = (float*)d_out;

    int B = out_size;                       // 256
    int S = in_sizes[1] / B;                // 2048

    crf_gold<<<B, 256>>>(logits, labels, lens, T, out, S);
    crf_fwd <<<B / 2, 64>>>(logits, lens, T, out, S);
}